// round 11
// baseline (speedup 1.0000x reference)
#include <cuda_runtime.h>
#include <math.h>
#include <stdint.h>

#define NN 50000
#define EE 800000
#define FIN 10
#define HH 64
#define LL 3

__device__ float d_hA[NN * HH];
__device__ float d_hB[NN * HH];
__device__ float d_agg[NN * HH];       // unnormalized per-node sums
__device__ float d_cnt[NN];
__device__ int   d_deg[NN];
__device__ int   d_off[NN];            // start of each node's bucket (unordered)
__device__ int   d_cur[NN];
__device__ int   d_total;
__device__ int   d_srcp[EE];           // src node per CSR slot
__device__ int   d_perm[EE];           // original edge id per CSR slot
__device__ float d_gcsr[LL * EE];      // gates in CSR order, per layer

// ---------------------------------------------------------------------------
// packed f32x2 helpers
// ---------------------------------------------------------------------------
__device__ __forceinline__ void ldsv2u64(uint32_t addr,
                                         unsigned long long& a,
                                         unsigned long long& b) {
    asm volatile("ld.shared.v2.u64 {%0,%1}, [%2];"
                 : "=l"(a), "=l"(b) : "r"(addr));
}
__device__ __forceinline__ void ffma2(unsigned long long& d,
                                      unsigned long long a,
                                      unsigned long long b) {
    asm("fma.rn.f32x2 %0, %1, %2, %0;" : "+l"(d) : "l"(a), "l"(b));
}
__device__ __forceinline__ float pairsum(unsigned long long v) {
    uint32_t lo, hi;
    asm("mov.b64 {%0,%1}, %2;" : "=r"(lo), "=r"(hi) : "l"(v));
    return __uint_as_float(lo) + __uint_as_float(hi);
}

// ---------------------------------------------------------------------------
// h = relu(x @ Wp + bp)
// ---------------------------------------------------------------------------
__global__ void proj_kernel(const float* __restrict__ x,
                            const float* __restrict__ Wp,
                            const float* __restrict__ bp) {
    __shared__ float Ws[FIN * HH];
    __shared__ float bs[HH];
    for (int i = threadIdx.x; i < FIN * HH; i += blockDim.x) Ws[i] = Wp[i];
    if (threadIdx.x < HH) bs[threadIdx.x] = bp[threadIdx.x];
    __syncthreads();

    int idx = blockIdx.x * blockDim.x + threadIdx.x;
    if (idx >= NN * HH) return;
    int i = idx >> 6;
    int j = idx & 63;
    float acc = bs[j];
#pragma unroll
    for (int k = 0; k < FIN; k++) acc = fmaf(x[i * FIN + k], Ws[k * HH + j], acc);
    d_hA[idx] = fmaxf(acc, 0.f);
}

// ---------------------------------------------------------------------------
// CSR build: count -> alloc (warp-aggregated atomic, order-free) -> fill
// ---------------------------------------------------------------------------
__global__ void count_kernel(const int* __restrict__ ei) {
    int e = blockIdx.x * blockDim.x + threadIdx.x;
    if (e >= EE) return;
    atomicAdd(&d_deg[ei[EE + e]], 1);
}

__global__ void alloc_kernel() {
    int nd = blockIdx.x * blockDim.x + threadIdx.x;
    int lane = threadIdx.x & 31;
    int deg = (nd < NN) ? d_deg[nd] : 0;
    // warp inclusive scan
    int sc = deg;
#pragma unroll
    for (int o = 1; o < 32; o <<= 1) {
        int v = __shfl_up_sync(0xffffffffu, sc, o);
        if (lane >= o) sc += v;
    }
    int wsum = __shfl_sync(0xffffffffu, sc, 31);
    int base = 0;
    if (lane == 31) base = atomicAdd(&d_total, wsum);
    base = __shfl_sync(0xffffffffu, base, 31);
    if (nd < NN) {
        int excl = base + sc - deg;
        d_off[nd] = excl;
        d_cur[nd] = excl;
    }
}

__global__ void fill_kernel(const int* __restrict__ ei) {
    int e = blockIdx.x * blockDim.x + threadIdx.x;
    if (e >= EE) return;
    int s = ei[e];
    int d = ei[EE + e];
    int p = atomicAdd(&d_cur[d], 1);
    d_srcp[p] = s;
    d_perm[p] = e;
}

// ---------------------------------------------------------------------------
// Gates for all 3 layers, written directly in CSR order.
// ---------------------------------------------------------------------------
__global__ void gatecsr_kernel(const float* __restrict__ ea,
                               const float* __restrict__ ew1,
                               const float* __restrict__ eb1,
                               const float* __restrict__ ew2,
                               const float* __restrict__ eb2) {
    __shared__ float W1[LL * 3 * 16];
    __shared__ float B1[LL * 16];
    __shared__ float W2[LL * 16];
    __shared__ float B2[LL];
    for (int i = threadIdx.x; i < LL * 3 * 16; i += blockDim.x) W1[i] = ew1[i];
    if (threadIdx.x < LL * 16) {
        B1[threadIdx.x] = eb1[threadIdx.x];
        W2[threadIdx.x] = ew2[threadIdx.x];
    }
    if (threadIdx.x < LL) B2[threadIdx.x] = eb2[threadIdx.x];
    __syncthreads();

    int p = blockIdx.x * blockDim.x + threadIdx.x;   // EE % 256 == 0
    int e = d_perm[p];
    float a0 = ea[e * 3 + 0];
    float a1 = ea[e * 3 + 1];
    float a2 = ea[e * 3 + 2];
#pragma unroll
    for (int l = 0; l < LL; l++) {
        float z = B2[l];
#pragma unroll
        for (int k = 0; k < 16; k++) {
            float hk = B1[l * 16 + k];
            hk = fmaf(a0, W1[l * 48 + 0 * 16 + k], hk);
            hk = fmaf(a1, W1[l * 48 + 1 * 16 + k], hk);
            hk = fmaf(a2, W1[l * 48 + 2 * 16 + k], hk);
            z = fmaf(fmaxf(hk, 0.f), W2[l * 16 + k], z);
        }
        d_gcsr[l * EE + p] = 1.f / (1.f + __expf(-z));
    }
}

// ---------------------------------------------------------------------------
// Gather kernel (per layer): warp per dst node, quarter-warp edge slots.
// Writes unnormalized agg sums + gate count. No smem -> max occupancy.
// ---------------------------------------------------------------------------
__global__ void __launch_bounds__(256)
gather_kernel(const float4* __restrict__ hin4,
              const float* __restrict__ gcsr_l) {
    int warp = threadIdx.x >> 5;
    int lane = threadIdx.x & 31;
    int qtr  = lane >> 3;
    int ql   = lane & 7;
    float4* agg4 = (float4*)d_agg;

    for (int nd = blockIdx.x * 8 + warp; nd < NN; nd += gridDim.x * 8) {
        int e0 = d_off[nd];
        int e1 = e0 + d_deg[nd];

        float a0 = 0.f, a1 = 0.f, a2 = 0.f, a3 = 0.f;
        float a4 = 0.f, a5 = 0.f, a6 = 0.f, a7 = 0.f;
        float cw = 0.f;

        for (int base = e0; base < e1; base += 32) {
            int n = e1 - base;
            if (n > 32) n = 32;
            int   s = 0;
            float w = 0.f;
            if (lane < n) {
                s = d_srcp[base + lane];
                w = gcsr_l[base + lane];
            }
            cw += w;
            for (int i = 0; i < n; i += 8) {
                int idx0 = i + qtr;
                int idx1 = i + 4 + qtr;
                int   s0 = __shfl_sync(0xffffffffu, s, idx0);
                float w0 = __shfl_sync(0xffffffffu, w, idx0);
                int   s1 = __shfl_sync(0xffffffffu, s, idx1);
                float w1 = __shfl_sync(0xffffffffu, w, idx1);
                float4 u0 = hin4[s0 * 16 + ql];
                float4 u1 = hin4[s0 * 16 + 8 + ql];
                float4 v0 = hin4[s1 * 16 + ql];
                float4 v1 = hin4[s1 * 16 + 8 + ql];
                a0 = fmaf(u0.x, w0, a0); a1 = fmaf(u0.y, w0, a1);
                a2 = fmaf(u0.z, w0, a2); a3 = fmaf(u0.w, w0, a3);
                a4 = fmaf(u1.x, w0, a4); a5 = fmaf(u1.y, w0, a5);
                a6 = fmaf(u1.z, w0, a6); a7 = fmaf(u1.w, w0, a7);
                a0 = fmaf(v0.x, w1, a0); a1 = fmaf(v0.y, w1, a1);
                a2 = fmaf(v0.z, w1, a2); a3 = fmaf(v0.w, w1, a3);
                a4 = fmaf(v1.x, w1, a4); a5 = fmaf(v1.y, w1, a5);
                a6 = fmaf(v1.z, w1, a6); a7 = fmaf(v1.w, w1, a7);
            }
        }
#pragma unroll
        for (int o = 8; o <= 16; o <<= 1) {
            a0 += __shfl_xor_sync(0xffffffffu, a0, o);
            a1 += __shfl_xor_sync(0xffffffffu, a1, o);
            a2 += __shfl_xor_sync(0xffffffffu, a2, o);
            a3 += __shfl_xor_sync(0xffffffffu, a3, o);
            a4 += __shfl_xor_sync(0xffffffffu, a4, o);
            a5 += __shfl_xor_sync(0xffffffffu, a5, o);
            a6 += __shfl_xor_sync(0xffffffffu, a6, o);
            a7 += __shfl_xor_sync(0xffffffffu, a7, o);
        }
#pragma unroll
        for (int o = 16; o > 0; o >>= 1)
            cw += __shfl_xor_sync(0xffffffffu, cw, o);

        if (qtr == 0)
            agg4[nd * 16 + ql] = make_float4(a0, a1, a2, a3);
        else if (qtr == 1)
            agg4[nd * 16 + 8 + ql] = make_float4(a4, a5, a6, a7);
        if (lane == 0) d_cnt[nd] = cw;
    }
}

// ---------------------------------------------------------------------------
// MLP kernel (per layer): warp per 8 nodes.
// Dynamic smem: Wq (32KB, k-interleaved float4) + ins (8 warps x 4KB).
// ---------------------------------------------------------------------------
__global__ void __launch_bounds__(256)
mlp_kernel(const float4* __restrict__ hin4,
           float* __restrict__ hout,
           const float* __restrict__ nw,
           const float* __restrict__ nb,
           const float* __restrict__ g,
           const float* __restrict__ b) {
    extern __shared__ float dyn[];
    float*  Wqf  = dyn;                    // 32 KB  (8192 floats)
    float*  insb = dyn + 8192;             // 8 warps * 1024 floats = 32 KB
    __shared__ float nbs[HH], gs[HH], bs[HH];

    for (int i = threadIdx.x; i < 2 * HH * HH; i += blockDim.x) {
        int k = i >> 6;
        int j = i & 63;
        Wqf[((k >> 2) * 64 + j) * 4 + (k & 3)] = nw[i];
    }
    if (threadIdx.x < HH) {
        nbs[threadIdx.x] = nb[threadIdx.x];
        gs[threadIdx.x]  = g[threadIdx.x];
        bs[threadIdx.x]  = b[threadIdx.x];
    }
    __syncthreads();

    int warp = threadIdx.x >> 5;
    int lane = threadIdx.x & 31;

    float* insw = insb + warp * 1024;      // 8 nodes x [h(64), agg(64)]
    float4* ins4 = (float4*)insw;
    uint32_t insAddr = (uint32_t)__cvta_generic_to_shared(insw);
    uint32_t wBase   = (uint32_t)__cvta_generic_to_shared(Wqf) + lane * 16;

    const float4* agg4 = (const float4*)d_agg;
    float bias0 = nbs[lane];
    float bias1 = nbs[lane + 32];

    for (int nd0 = (blockIdx.x * 8 + warp) * 8; nd0 < NN; nd0 += gridDim.x * 64) {
        // stage h and normalized agg for 8 nodes (coalesced float4)
        float invv = 0.f;
        if (lane < 8) invv = 1.f / fmaxf(d_cnt[nd0 + lane], 1e-12f);
#pragma unroll
        for (int i = 0; i < 4; i++) {
            int idx = i * 32 + lane;       // 0..127
            int nloc = idx >> 4;
            int slot = idx & 15;
            ins4[nloc * 32 + slot] = hin4[(nd0 + nloc) * 16 + slot];
            float invn = __shfl_sync(0xffffffffu, invv, nloc);
            float4 v = agg4[(nd0 + nloc) * 16 + slot];
            ins4[nloc * 32 + 16 + slot] =
                make_float4(v.x * invn, v.y * invn, v.z * invn, v.w * invn);
        }
        __syncwarp();

        unsigned long long aA[8], aB[8];
#pragma unroll
        for (int n = 0; n < 8; n++) { aA[n] = 0ull; aB[n] = 0ull; }

        uint32_t wAddr = wBase;
#pragma unroll
        for (int t = 0; t < 32; t++) {
            unsigned long long wa0, wa1, wb0, wb1;
            ldsv2u64(wAddr, wa0, wa1);          // j = lane
            ldsv2u64(wAddr + 512, wb0, wb1);    // j = lane+32
#pragma unroll
            for (int n = 0; n < 8; n++) {
                unsigned long long x0, x1;
                ldsv2u64(insAddr + n * 512 + t * 16, x0, x1);
                ffma2(aA[n], x0, wa0); ffma2(aA[n], x1, wa1);
                ffma2(aB[n], x0, wb0); ffma2(aB[n], x1, wb1);
            }
            wAddr += 1024;
        }

#pragma unroll
        for (int n = 0; n < 8; n++) {
            int nd = nd0 + n;
            float hl = insw[n * 128 + lane];
            float hh = insw[n * 128 + 32 + lane];
            float v0 = hl + fmaxf(pairsum(aA[n]) + bias0, 0.f);
            float v1 = hh + fmaxf(pairsum(aB[n]) + bias1, 0.f);

            float s1 = v0 + v1;
#pragma unroll
            for (int o = 16; o > 0; o >>= 1)
                s1 += __shfl_xor_sync(0xffffffffu, s1, o);
            float mu = s1 * (1.f / HH);
            float t0 = v0 - mu, t1 = v1 - mu;
            float s2 = t0 * t0 + t1 * t1;
#pragma unroll
            for (int o = 16; o > 0; o >>= 1)
                s2 += __shfl_xor_sync(0xffffffffu, s2, o);
            float var = s2 * (1.f / HH);
            float r = rsqrtf(var + 1e-5f);

            hout[nd * HH + lane]      = t0 * r * gs[lane]      + bs[lane];
            hout[nd * HH + 32 + lane] = t1 * r * gs[lane + 32] + bs[lane + 32];
        }
        __syncwarp();
    }
}

// ---------------------------------------------------------------------------
// Head: out = relu(h @ hw1 + hb1) @ hw2 + hb2
// ---------------------------------------------------------------------------
__global__ void head_kernel(const float* __restrict__ hsrc,
                            const float* __restrict__ hw1,
                            const float* __restrict__ hb1,
                            const float* __restrict__ hw2,
                            const float* __restrict__ hb2,
                            float* __restrict__ out) {
    __shared__ float W1[HH * 32];
    __shared__ float b1s[32], w2s[32];
    for (int i = threadIdx.x; i < HH * 32; i += blockDim.x) W1[i] = hw1[i];
    if (threadIdx.x < 32) {
        b1s[threadIdx.x] = hb1[threadIdx.x];
        w2s[threadIdx.x] = hw2[threadIdx.x];
    }
    __syncthreads();

    int lane = threadIdx.x & 31;
    int warp = threadIdx.x >> 5;
    float bb2 = hb2[0];

    for (int node = blockIdx.x * 8 + warp; node < NN; node += gridDim.x * 8) {
        float hlo = hsrc[node * HH + lane];
        float hhi = hsrc[node * HH + 32 + lane];
        float acc = b1s[lane];
#pragma unroll
        for (int k = 0; k < 32; k++) {
            float hk = __shfl_sync(0xffffffffu, hlo, k);
            acc = fmaf(hk, W1[k * 32 + lane], acc);
        }
#pragma unroll
        for (int k = 0; k < 32; k++) {
            float hk = __shfl_sync(0xffffffffu, hhi, k);
            acc = fmaf(hk, W1[(32 + k) * 32 + lane], acc);
        }
        float p = fmaxf(acc, 0.f) * w2s[lane];
#pragma unroll
        for (int o = 16; o > 0; o >>= 1)
            p += __shfl_xor_sync(0xffffffffu, p, o);
        if (lane == 0) out[node] = p + bb2;
    }
}

// ---------------------------------------------------------------------------
extern "C" void kernel_launch(void* const* d_in, const int* in_sizes, int n_in,
                              void* d_out, int out_size) {
    const float* x   = (const float*)d_in[0];
    const int*   ei  = (const int*)  d_in[1];
    const float* ea  = (const float*)d_in[2];
    const float* Wp  = (const float*)d_in[3];
    const float* bp  = (const float*)d_in[4];
    const float* ew1 = (const float*)d_in[5];
    const float* eb1 = (const float*)d_in[6];
    const float* ew2 = (const float*)d_in[7];
    const float* eb2 = (const float*)d_in[8];
    const float* nw  = (const float*)d_in[9];
    const float* nb  = (const float*)d_in[10];
    const float* lng = (const float*)d_in[11];
    const float* lnb = (const float*)d_in[12];
    const float* hw1 = (const float*)d_in[13];
    const float* hb1 = (const float*)d_in[14];
    const float* hw2 = (const float*)d_in[15];
    const float* hb2 = (const float*)d_in[16];
    float* out = (float*)d_out;

    void* degPtr = nullptr; void* totPtr = nullptr;
    cudaGetSymbolAddress(&degPtr, d_deg);
    cudaGetSymbolAddress(&totPtr, d_total);
    float* hA = nullptr; float* hB = nullptr; float* gcsr = nullptr;
    cudaGetSymbolAddress((void**)&hA, d_hA);
    cudaGetSymbolAddress((void**)&hB, d_hB);
    cudaGetSymbolAddress((void**)&gcsr, d_gcsr);

    static bool attrSet = false;
    if (!attrSet) {
        cudaFuncSetAttribute(mlp_kernel,
                             cudaFuncAttributeMaxDynamicSharedMemorySize,
                             16384 * sizeof(float));
        attrSet = true;
    }
    const int mlpSmem = 16384 * sizeof(float);   // 64 KB

    proj_kernel<<<(NN * HH + 255) / 256, 256>>>(x, Wp, bp);

    cudaMemsetAsync(degPtr, 0, (size_t)NN * sizeof(int));
    cudaMemsetAsync(totPtr, 0, sizeof(int));
    count_kernel<<<(EE + 255) / 256, 256>>>(ei);
    alloc_kernel<<<(NN + 255) / 256, 256>>>();
    fill_kernel<<<(EE + 255) / 256, 256>>>(ei);
    gatecsr_kernel<<<EE / 256, 256>>>(ea, ew1, eb1, ew2, eb2);

    for (int l = 0; l < LL; l++) {
        const float* hin  = (l & 1) ? hB : hA;
        float*       hout = (l & 1) ? hA : hB;
        gather_kernel<<<1184, 256>>>((const float4*)hin,
                                     gcsr + (size_t)l * EE);
        mlp_kernel<<<444, 256, mlpSmem>>>((const float4*)hin, hout,
                                          nw + l * 2 * HH * HH, nb + l * HH,
                                          lng + l * HH, lnb + l * HH);
    }

    head_kernel<<<592, 256>>>(hB, hw1, hb1, hw2, hb2, out);
}

// round 14
// speedup vs baseline: 1.0342x; 1.0342x over previous
#include <cuda_runtime.h>
#include <math.h>
#include <stdint.h>

#define NN 50000
#define EE 800000
#define FIN 10
#define HH 64
#define LL 3

__device__ float d_hA[NN * HH];
__device__ float d_hB[NN * HH];
__device__ int   d_deg[NN];
__device__ int   d_off[NN];            // bucket start per node (unordered)
__device__ int   d_cur[NN];
__device__ int   d_total;
__device__ int   d_srcp[EE];           // src node per CSR slot
__device__ int   d_perm[EE];           // original edge id per CSR slot
__device__ float d_gcsr[LL * EE];      // gates in CSR order, per layer

// ---------------------------------------------------------------------------
// packed f32x2 helpers
// ---------------------------------------------------------------------------
__device__ __forceinline__ void ldsv2u64(uint32_t addr,
                                         unsigned long long& a,
                                         unsigned long long& b) {
    asm volatile("ld.shared.v2.u64 {%0,%1}, [%2];"
                 : "=l"(a), "=l"(b) : "r"(addr));
}
__device__ __forceinline__ void ffma2(unsigned long long& d,
                                      unsigned long long a,
                                      unsigned long long b) {
    asm("fma.rn.f32x2 %0, %1, %2, %0;" : "+l"(d) : "l"(a), "l"(b));
}
__device__ __forceinline__ float pairsum(unsigned long long v) {
    uint32_t lo, hi;
    asm("mov.b64 {%0,%1}, %2;" : "=r"(lo), "=r"(hi) : "l"(v));
    return __uint_as_float(lo) + __uint_as_float(hi);
}

// ---------------------------------------------------------------------------
// h = relu(x @ Wp + bp)
// ---------------------------------------------------------------------------
__global__ void proj_kernel(const float* __restrict__ x,
                            const float* __restrict__ Wp,
                            const float* __restrict__ bp) {
    __shared__ float Ws[FIN * HH];
    __shared__ float bs[HH];
    for (int i = threadIdx.x; i < FIN * HH; i += blockDim.x) Ws[i] = Wp[i];
    if (threadIdx.x < HH) bs[threadIdx.x] = bp[threadIdx.x];
    __syncthreads();

    int idx = blockIdx.x * blockDim.x + threadIdx.x;
    if (idx >= NN * HH) return;
    int i = idx >> 6;
    int j = idx & 63;
    float acc = bs[j];
#pragma unroll
    for (int k = 0; k < FIN; k++) acc = fmaf(x[i * FIN + k], Ws[k * HH + j], acc);
    d_hA[idx] = fmaxf(acc, 0.f);
}

// ---------------------------------------------------------------------------
// CSR build: count -> alloc (warp-aggregated atomic) -> fill (perm only)
// ---------------------------------------------------------------------------
__global__ void count_kernel(const int* __restrict__ ei) {
    int e = blockIdx.x * blockDim.x + threadIdx.x;
    if (e >= EE) return;
    atomicAdd(&d_deg[ei[EE + e]], 1);
}

__global__ void alloc_kernel() {
    int nd = blockIdx.x * blockDim.x + threadIdx.x;
    int lane = threadIdx.x & 31;
    int deg = (nd < NN) ? d_deg[nd] : 0;
    int sc = deg;
#pragma unroll
    for (int o = 1; o < 32; o <<= 1) {
        int v = __shfl_up_sync(0xffffffffu, sc, o);
        if (lane >= o) sc += v;
    }
    int wsum = __shfl_sync(0xffffffffu, sc, 31);
    int base = 0;
    if (lane == 31) base = atomicAdd(&d_total, wsum);
    base = __shfl_sync(0xffffffffu, base, 31);
    if (nd < NN) {
        int excl = base + sc - deg;
        d_off[nd] = excl;
        d_cur[nd] = excl;
    }
}

__global__ void fill_kernel(const int* __restrict__ ei) {
    int e = blockIdx.x * blockDim.x + threadIdx.x;
    if (e >= EE) return;
    int d = ei[EE + e];
    int p = atomicAdd(&d_cur[d], 1);
    d_perm[p] = e;
}

// ---------------------------------------------------------------------------
// Gates for all 3 layers (CSR order) + srcp materialization (coalesced write).
// ---------------------------------------------------------------------------
__global__ void gatecsr_kernel(const int* __restrict__ ei,
                               const float* __restrict__ ea,
                               const float* __restrict__ ew1,
                               const float* __restrict__ eb1,
                               const float* __restrict__ ew2,
                               const float* __restrict__ eb2) {
    __shared__ float W1[LL * 3 * 16];
    __shared__ float B1[LL * 16];
    __shared__ float W2[LL * 16];
    __shared__ float B2[LL];
    for (int i = threadIdx.x; i < LL * 3 * 16; i += blockDim.x) W1[i] = ew1[i];
    if (threadIdx.x < LL * 16) {
        B1[threadIdx.x] = eb1[threadIdx.x];
        W2[threadIdx.x] = ew2[threadIdx.x];
    }
    if (threadIdx.x < LL) B2[threadIdx.x] = eb2[threadIdx.x];
    __syncthreads();

    int p = blockIdx.x * blockDim.x + threadIdx.x;   // EE % 256 == 0
    int e = d_perm[p];
    d_srcp[p] = ei[e];                   // coalesced store, L2-hot random read
    float a0 = ea[e * 3 + 0];
    float a1 = ea[e * 3 + 1];
    float a2 = ea[e * 3 + 2];
#pragma unroll
    for (int l = 0; l < LL; l++) {
        float z = B2[l];
#pragma unroll
        for (int k = 0; k < 16; k++) {
            float hk = B1[l * 16 + k];
            hk = fmaf(a0, W1[l * 48 + 0 * 16 + k], hk);
            hk = fmaf(a1, W1[l * 48 + 1 * 16 + k], hk);
            hk = fmaf(a2, W1[l * 48 + 2 * 16 + k], hk);
            z = fmaf(fmaxf(hk, 0.f), W2[l * 16 + k], z);
        }
        d_gcsr[l * EE + p] = 1.f / (1.f + __expf(-z));
    }
}

// ---------------------------------------------------------------------------
// Fused layer: warp per 4 dst nodes (best-known R9 version; e1 = e0 + deg).
// ---------------------------------------------------------------------------
__global__ void __launch_bounds__(256)
layer_kernel(const float4* __restrict__ hin4,
             float* __restrict__ hout,
             const float* __restrict__ gcsr_l,
             const float* __restrict__ nw,
             const float* __restrict__ nb,
             const float* __restrict__ g,
             const float* __restrict__ b) {
    __shared__ float4 Wq[32 * 64];         // 32 KB  (k-interleaved float4)
    __shared__ float nbs[HH], gs[HH], bs[HH];
    __shared__ float ins[8][4 * 2 * HH];   // per-warp, 4 nodes x [h(64),agg(64)]

    {
        float* Wqf = (float*)Wq;
        for (int i = threadIdx.x; i < 2 * HH * HH; i += blockDim.x) {
            int k = i >> 6;
            int j = i & 63;
            Wqf[((k >> 2) * 64 + j) * 4 + (k & 3)] = nw[i];
        }
    }
    if (threadIdx.x < HH) {
        nbs[threadIdx.x] = nb[threadIdx.x];
        gs[threadIdx.x]  = g[threadIdx.x];
        bs[threadIdx.x]  = b[threadIdx.x];
    }
    __syncthreads();

    int warp = threadIdx.x >> 5;
    int lane = threadIdx.x & 31;
    int qtr  = lane >> 3;
    int ql   = lane & 7;

    float* insw = &ins[warp][0];
    float4* ins4 = (float4*)insw;
    uint32_t insAddr = (uint32_t)__cvta_generic_to_shared(insw);
    uint32_t wBase   = (uint32_t)__cvta_generic_to_shared(Wq) + lane * 16;

    for (int nd0 = (blockIdx.x * 8 + warp) * 4; nd0 < NN; nd0 += gridDim.x * 32) {
        // ---- Phase A: gather 4 nodes ----
#pragma unroll
        for (int nloc = 0; nloc < 4; nloc++) {
            int nd = nd0 + nloc;
            int e0 = d_off[nd];
            int e1 = e0 + d_deg[nd];

            float a0 = 0.f, a1 = 0.f, a2 = 0.f, a3 = 0.f;
            float a4 = 0.f, a5 = 0.f, a6 = 0.f, a7 = 0.f;
            float cw = 0.f;

            for (int base = e0; base < e1; base += 32) {
                int n = e1 - base;
                if (n > 32) n = 32;
                int   s = 0;
                float w = 0.f;
                if (lane < n) {
                    s = d_srcp[base + lane];
                    w = gcsr_l[base + lane];
                }
                cw += w;
                for (int i = 0; i < n; i += 8) {
                    int idx0 = i + qtr;
                    int idx1 = i + 4 + qtr;
                    int   s0 = __shfl_sync(0xffffffffu, s, idx0);
                    float w0 = __shfl_sync(0xffffffffu, w, idx0);
                    int   s1 = __shfl_sync(0xffffffffu, s, idx1);
                    float w1 = __shfl_sync(0xffffffffu, w, idx1);
                    float4 u0 = hin4[s0 * 16 + ql];
                    float4 u1 = hin4[s0 * 16 + 8 + ql];
                    float4 v0 = hin4[s1 * 16 + ql];
                    float4 v1 = hin4[s1 * 16 + 8 + ql];
                    a0 = fmaf(u0.x, w0, a0); a1 = fmaf(u0.y, w0, a1);
                    a2 = fmaf(u0.z, w0, a2); a3 = fmaf(u0.w, w0, a3);
                    a4 = fmaf(u1.x, w0, a4); a5 = fmaf(u1.y, w0, a5);
                    a6 = fmaf(u1.z, w0, a6); a7 = fmaf(u1.w, w0, a7);
                    a0 = fmaf(v0.x, w1, a0); a1 = fmaf(v0.y, w1, a1);
                    a2 = fmaf(v0.z, w1, a2); a3 = fmaf(v0.w, w1, a3);
                    a4 = fmaf(v1.x, w1, a4); a5 = fmaf(v1.y, w1, a5);
                    a6 = fmaf(v1.z, w1, a6); a7 = fmaf(v1.w, w1, a7);
                }
            }
#pragma unroll
            for (int o = 8; o <= 16; o <<= 1) {
                a0 += __shfl_xor_sync(0xffffffffu, a0, o);
                a1 += __shfl_xor_sync(0xffffffffu, a1, o);
                a2 += __shfl_xor_sync(0xffffffffu, a2, o);
                a3 += __shfl_xor_sync(0xffffffffu, a3, o);
                a4 += __shfl_xor_sync(0xffffffffu, a4, o);
                a5 += __shfl_xor_sync(0xffffffffu, a5, o);
                a6 += __shfl_xor_sync(0xffffffffu, a6, o);
                a7 += __shfl_xor_sync(0xffffffffu, a7, o);
            }
#pragma unroll
            for (int o = 16; o > 0; o >>= 1)
                cw += __shfl_xor_sync(0xffffffffu, cw, o);

            float inv = 1.f / fmaxf(cw, 1e-12f);
            if (lane < 16)
                ins4[nloc * 32 + lane] = hin4[(size_t)nd * 16 + lane];
            if (qtr == 0)
                ins4[nloc * 32 + 16 + ql] =
                    make_float4(a0 * inv, a1 * inv, a2 * inv, a3 * inv);
            else if (qtr == 1)
                ins4[nloc * 32 + 16 + 8 + ql] =
                    make_float4(a4 * inv, a5 * inv, a6 * inv, a7 * inv);
            __syncwarp();
        }

        // ---- Phase B: joint MLP (FFMA2) ----
        unsigned long long aA0 = 0, aA1 = 0, aA2 = 0, aA3 = 0;
        unsigned long long aB0 = 0, aB1 = 0, aB2 = 0, aB3 = 0;
        uint32_t wAddr = wBase;
#pragma unroll
        for (int t = 0; t < 32; t++) {
            unsigned long long wa0, wa1, wb0, wb1;
            ldsv2u64(wAddr, wa0, wa1);
            ldsv2u64(wAddr + 512, wb0, wb1);
            unsigned long long x0, x1;
            ldsv2u64(insAddr + 0 * 512 + t * 16, x0, x1);
            ffma2(aA0, x0, wa0); ffma2(aA0, x1, wa1);
            ffma2(aB0, x0, wb0); ffma2(aB0, x1, wb1);
            ldsv2u64(insAddr + 1 * 512 + t * 16, x0, x1);
            ffma2(aA1, x0, wa0); ffma2(aA1, x1, wa1);
            ffma2(aB1, x0, wb0); ffma2(aB1, x1, wb1);
            ldsv2u64(insAddr + 2 * 512 + t * 16, x0, x1);
            ffma2(aA2, x0, wa0); ffma2(aA2, x1, wa1);
            ffma2(aB2, x0, wb0); ffma2(aB2, x1, wb1);
            ldsv2u64(insAddr + 3 * 512 + t * 16, x0, x1);
            ffma2(aA3, x0, wa0); ffma2(aA3, x1, wa1);
            ffma2(aB3, x0, wb0); ffma2(aB3, x1, wb1);
            wAddr += 1024;
        }

        float o0n[4], o1n[4];
        o0n[0] = pairsum(aA0); o0n[1] = pairsum(aA1);
        o0n[2] = pairsum(aA2); o0n[3] = pairsum(aA3);
        o1n[0] = pairsum(aB0); o1n[1] = pairsum(aB1);
        o1n[2] = pairsum(aB2); o1n[3] = pairsum(aB3);

        float bias0 = nbs[lane];
        float bias1 = nbs[lane + 32];

        // ---- Phase C: residual + LN per node ----
#pragma unroll
        for (int nloc = 0; nloc < 4; nloc++) {
            int nd = nd0 + nloc;
            float hl = insw[nloc * 128 + lane];
            float hh = insw[nloc * 128 + 32 + lane];
            float v0 = hl + fmaxf(o0n[nloc] + bias0, 0.f);
            float v1 = hh + fmaxf(o1n[nloc] + bias1, 0.f);

            float s1 = v0 + v1;
#pragma unroll
            for (int o = 16; o > 0; o >>= 1)
                s1 += __shfl_xor_sync(0xffffffffu, s1, o);
            float mu = s1 * (1.f / HH);
            float t0 = v0 - mu, t1 = v1 - mu;
            float s2 = t0 * t0 + t1 * t1;
#pragma unroll
            for (int o = 16; o > 0; o >>= 1)
                s2 += __shfl_xor_sync(0xffffffffu, s2, o);
            float var = s2 * (1.f / HH);
            float r = rsqrtf(var + 1e-5f);

            hout[nd * HH + lane]      = t0 * r * gs[lane]      + bs[lane];
            hout[nd * HH + 32 + lane] = t1 * r * gs[lane + 32] + bs[lane + 32];
        }
        __syncwarp();
    }
}

// ---------------------------------------------------------------------------
// Head: out = relu(h @ hw1 + hb1) @ hw2 + hb2
// ---------------------------------------------------------------------------
__global__ void head_kernel(const float* __restrict__ hsrc,
                            const float* __restrict__ hw1,
                            const float* __restrict__ hb1,
                            const float* __restrict__ hw2,
                            const float* __restrict__ hb2,
                            float* __restrict__ out) {
    __shared__ float W1[HH * 32];
    __shared__ float b1s[32], w2s[32];
    for (int i = threadIdx.x; i < HH * 32; i += blockDim.x) W1[i] = hw1[i];
    if (threadIdx.x < 32) {
        b1s[threadIdx.x] = hb1[threadIdx.x];
        w2s[threadIdx.x] = hw2[threadIdx.x];
    }
    __syncthreads();

    int lane = threadIdx.x & 31;
    int warp = threadIdx.x >> 5;
    float bb2 = hb2[0];

    for (int node = blockIdx.x * 8 + warp; node < NN; node += gridDim.x * 8) {
        float hlo = hsrc[node * HH + lane];
        float hhi = hsrc[node * HH + 32 + lane];
        float acc = b1s[lane];
#pragma unroll
        for (int k = 0; k < 32; k++) {
            float hk = __shfl_sync(0xffffffffu, hlo, k);
            acc = fmaf(hk, W1[k * 32 + lane], acc);
        }
#pragma unroll
        for (int k = 0; k < 32; k++) {
            float hk = __shfl_sync(0xffffffffu, hhi, k);
            acc = fmaf(hk, W1[(32 + k) * 32 + lane], acc);
        }
        float p = fmaxf(acc, 0.f) * w2s[lane];
#pragma unroll
        for (int o = 16; o > 0; o >>= 1)
            p += __shfl_xor_sync(0xffffffffu, p, o);
        if (lane == 0) out[node] = p + bb2;
    }
}

// ---------------------------------------------------------------------------
extern "C" void kernel_launch(void* const* d_in, const int* in_sizes, int n_in,
                              void* d_out, int out_size) {
    const float* x   = (const float*)d_in[0];
    const int*   ei  = (const int*)  d_in[1];
    const float* ea  = (const float*)d_in[2];
    const float* Wp  = (const float*)d_in[3];
    const float* bp  = (const float*)d_in[4];
    const float* ew1 = (const float*)d_in[5];
    const float* eb1 = (const float*)d_in[6];
    const float* ew2 = (const float*)d_in[7];
    const float* eb2 = (const float*)d_in[8];
    const float* nw  = (const float*)d_in[9];
    const float* nb  = (const float*)d_in[10];
    const float* lng = (const float*)d_in[11];
    const float* lnb = (const float*)d_in[12];
    const float* hw1 = (const float*)d_in[13];
    const float* hb1 = (const float*)d_in[14];
    const float* hw2 = (const float*)d_in[15];
    const float* hb2 = (const float*)d_in[16];
    float* out = (float*)d_out;

    void* degPtr = nullptr; void* totPtr = nullptr;
    cudaGetSymbolAddress(&degPtr, d_deg);
    cudaGetSymbolAddress(&totPtr, d_total);
    float* hA = nullptr; float* hB = nullptr; float* gcsr = nullptr;
    cudaGetSymbolAddress((void**)&hA, d_hA);
    cudaGetSymbolAddress((void**)&hB, d_hB);
    cudaGetSymbolAddress((void**)&gcsr, d_gcsr);

    proj_kernel<<<(NN * HH + 255) / 256, 256>>>(x, Wp, bp);

    cudaMemsetAsync(degPtr, 0, (size_t)NN * sizeof(int));
    cudaMemsetAsync(totPtr, 0, sizeof(int));
    count_kernel<<<(EE + 255) / 256, 256>>>(ei);
    alloc_kernel<<<(NN + 255) / 256, 256>>>();
    fill_kernel<<<(EE + 255) / 256, 256>>>(ei);
    gatecsr_kernel<<<EE / 256, 256>>>(ei, ea, ew1, eb1, ew2, eb2);

    for (int l = 0; l < LL; l++) {
        const float* hin  = (l & 1) ? hB : hA;
        float*       hout = (l & 1) ? hA : hB;
        layer_kernel<<<592, 256>>>((const float4*)hin, hout,
                                   gcsr + (size_t)l * EE,
                                   nw + l * 2 * HH * HH, nb + l * HH,
                                   lng + l * HH, lnb + l * HH);
    }

    head_kernel<<<592, 256>>>(hB, hw1, hb1, hw2, hb2, out);
}